// round 10
// baseline (speedup 1.0000x reference)
#include <cuda_runtime.h>
#include <cuda_fp16.h>
#include <cstdint>

#define NPTS 100000
#define NTILES 1563            // ceil(100000/64)
typedef unsigned long long ull;

// Scratch (device globals). q,o fp32; k,v fp16 interleaved: row = [k(64) | v(64)].
__device__ float  g_q[NPTS * 64];
__device__ __half g_kv[NPTS * 128];
__device__ float  g_o[NPTS * 64];

// ---- packed f32x2 helpers ----
__device__ __forceinline__ ull pack2(float x) {
    ull r;
    asm("mov.b64 %0, {%1, %1};" : "=l"(r) : "r"(__float_as_uint(x)));
    return r;
}
__device__ __forceinline__ ull packxy(float x, float y) {
    ull r;
    asm("mov.b64 %0, {%1, %2};" : "=l"(r) : "f"(x), "f"(y));
    return r;
}
__device__ __forceinline__ float2 unpack2(ull a) {
    float2 f;
    asm("mov.b64 {%0, %1}, %2;" : "=f"(f.x), "=f"(f.y) : "l"(a));
    return f;
}
__device__ __forceinline__ ull fma2(ull a, ull b, ull c) {
    ull d;
    asm("fma.rn.f32x2 %0, %1, %2, %3;" : "=l"(d) : "l"(a), "l"(b), "l"(c));
    return d;
}

// load one 64-point feats tile into 4 float4 regs per thread (coalesced LDG.128)
__device__ __forceinline__ void load_tile(const float* __restrict__ src,
                                          int base, float4* buf) {
    #pragma unroll
    for (int k2 = 0; k2 < 4; ++k2) {
        const int fi = (threadIdx.x + k2 * 256) * 4;   // float index in tile
        const int n = base + (fi >> 6);
        buf[k2] = (n < NPTS) ? *(const float4*)&src[(size_t)base * 64 + fi]
                             : make_float4(0.f, 0.f, 0.f, 0.f);
    }
}

// store the 4 float4 regs into fdup as duplicated {f,f} pairs (STS.128 x2 each)
__device__ __forceinline__ void store_tile_dup(ull (*fdup)[64], const float4* buf) {
    #pragma unroll
    for (int k2 = 0; k2 < 4; ++k2) {
        const int fi = (threadIdx.x + k2 * 256) * 4;
        const int p = fi >> 6, c = fi & 63;
        ulonglong2 a, b;
        a.x = pack2(buf[k2].x); a.y = pack2(buf[k2].y);
        b.x = pack2(buf[k2].z); b.y = pack2(buf[k2].w);
        *(ulonglong2*)&fdup[p][c]     = a;
        *(ulonglong2*)&fdup[p][c + 2] = b;
    }
}

// ============================================================================
// Kernel 1: q,k,v = feats @ {Wq,Wk,Wv}. PERSISTENT: weights loaded once per
// block; loop over tiles with register-prefetched feats (LDG hidden by FFMA2).
// Thread = (4 channels, 4 points). Per i-step: 3 LDS.128 + 4 LDS.64 + 24 FFMA2.
// ============================================================================
__global__ void __launch_bounds__(256) proj_qkv_kernel(
    const float* __restrict__ feats,
    const float* __restrict__ Wq,
    const float* __restrict__ Wk,
    const float* __restrict__ Wv)
{
    __shared__ __align__(16) float wq_s[4096];
    __shared__ __align__(16) float wk_s[4096];
    __shared__ __align__(16) float wv_s[4096];
    __shared__ __align__(16) ull   fdup[64][64];   // 32 KB

    const int tid = threadIdx.x;
    for (int i = tid; i < 4096; i += 256) {
        wq_s[i] = Wq[i]; wk_s[i] = Wk[i]; wv_s[i] = Wv[i];
    }

    const int c4 = tid & 15;    // channels 4*c4 .. 4*c4+3
    const int pr = tid >> 4;    // points pr, pr+16, pr+32, pr+48

    float4 buf[4];
    int t = blockIdx.x;
    if (t < NTILES) load_tile(feats, t * 64, buf);

    for (; t < NTILES; t += gridDim.x) {
        const int base = t * 64;
        store_tile_dup(fdup, buf);
        __syncthreads();                       // fdup (and, first iter, weights) ready

        const int tn = t + gridDim.x;
        if (tn < NTILES) load_tile(feats, tn * 64, buf);   // prefetch next tile

        ull aq[4][2], ak[4][2], av[4][2];
        #pragma unroll
        for (int pp = 0; pp < 4; ++pp)
            #pragma unroll
            for (int h = 0; h < 2; ++h) { aq[pp][h] = 0; ak[pp][h] = 0; av[pp][h] = 0; }

        #pragma unroll
        for (int i = 0; i < 64; ++i) {
            const ulonglong2 wq01 = *(const ulonglong2*)&wq_s[i * 64 + 4 * c4];
            const ulonglong2 wk01 = *(const ulonglong2*)&wk_s[i * 64 + 4 * c4];
            const ulonglong2 wv01 = *(const ulonglong2*)&wv_s[i * 64 + 4 * c4];
            #pragma unroll
            for (int pp = 0; pp < 4; ++pp) {
                const ull f = fdup[pr + 16 * pp][i];    // broadcast LDS.64
                aq[pp][0] = fma2(f, wq01.x, aq[pp][0]);
                aq[pp][1] = fma2(f, wq01.y, aq[pp][1]);
                ak[pp][0] = fma2(f, wk01.x, ak[pp][0]);
                ak[pp][1] = fma2(f, wk01.y, ak[pp][1]);
                av[pp][0] = fma2(f, wv01.x, av[pp][0]);
                av[pp][1] = fma2(f, wv01.y, av[pp][1]);
            }
        }

        #pragma unroll
        for (int pp = 0; pp < 4; ++pp) {
            const int n = base + pr + 16 * pp;
            if (n < NPTS) {
                *(ull*)&g_q[n * 64 + 4 * c4]     = aq[pp][0];
                *(ull*)&g_q[n * 64 + 4 * c4 + 2] = aq[pp][1];
                const float2 k0 = unpack2(ak[pp][0]), k1 = unpack2(ak[pp][1]);
                const float2 v0 = unpack2(av[pp][0]), v1 = unpack2(av[pp][1]);
                *(__half2*)&g_kv[n * 128 + 4 * c4]          = __floats2half2_rn(k0.x, k0.y);
                *(__half2*)&g_kv[n * 128 + 4 * c4 + 2]      = __floats2half2_rn(k1.x, k1.y);
                *(__half2*)&g_kv[n * 128 + 64 + 4 * c4]     = __floats2half2_rn(v0.x, v0.y);
                *(__half2*)&g_kv[n * 128 + 64 + 4 * c4 + 2] = __floats2half2_rn(v1.x, v1.y);
            }
        }
        __syncthreads();                       // all reads of fdup done
    }
}

// ============================================================================
// Kernel 2: attention gather + softmax + value mix. PERSISTENT grid-stride,
// one warp per point per iteration (kills the 14-wave scheduling overhead).
// Lane-split softmax: each lane of a 4-lane head group exponentiates only 4
// of the 16 scores (4 MUFU instead of 16), results shuffle-gathered.
// ============================================================================
__global__ void __launch_bounds__(256) attn_kernel(const int* __restrict__ knn)
{
    const int l = threadIdx.x & 31;
    const int gw = blockIdx.x * 8 + (threadIdx.x >> 5);   // global warp id
    const int stride = gridDim.x * 8;
    const int jl   = l & 3;        // lane-within-head-group: owns j = 4*jl..4*jl+3
    const int gbase = l & ~3;      // first lane of this head group

    for (int n = gw; n < NPTS; n += stride) {
        int idxv = 0;
        if (l < 16) idxv = knn[n * 16 + l];
        int idxs[16];
        #pragma unroll
        for (int j = 0; j < 16; ++j)
            idxs[j] = __shfl_sync(0xffffffffu, idxv, j);

        const float2 q2 = *(const float2*)&g_q[n * 64 + 2 * l];

        // prefetch all 16 k rows AND 16 v rows (coalesced half2, MLP=32)
        __half2 kh[16], vh[16];
        #pragma unroll
        for (int j = 0; j < 16; ++j) {
            kh[j] = *(const __half2*)&g_kv[idxs[j] * 128 + 2 * l];
            vh[j] = *(const __half2*)&g_kv[idxs[j] * 128 + 64 + 2 * l];
        }

        float a[16];
        #pragma unroll
        for (int j = 0; j < 16; ++j) {
            const float2 kf = __half22float2(kh[j]);
            float p = q2.x * kf.x + q2.y * kf.y;
            p += __shfl_xor_sync(0xffffffffu, p, 1);
            p += __shfl_xor_sync(0xffffffffu, p, 2);   // 4-lane group = one head
            a[j] = p * 0.3535533905932738f;            // * 1/sqrt(8)
        }

        // max over 16 neighbors (a[] identical within head group)
        float m = a[0];
        #pragma unroll
        for (int j = 1; j < 16; ++j) m = fmaxf(m, a[j]);

        // lane-split exp: this lane handles j = 4*jl .. 4*jl+3
        float e[4];
        float s = 0.f;
        #pragma unroll
        for (int t = 0; t < 4; ++t) {
            e[t] = exp2f((a[4 * jl + t] - m) * 1.4426950408889634f);
            s += e[t];
        }
        s += __shfl_xor_sync(0xffffffffu, s, 1);
        s += __shfl_xor_sync(0xffffffffu, s, 2);       // sum over head group
        const float inv = __fdividef(1.f, s);
        #pragma unroll
        for (int t = 0; t < 4; ++t) e[t] *= inv;

        // attended value: gather a[j] from lane gbase + (j>>2) within the group
        float2 o2 = make_float2(0.f, 0.f);
        #pragma unroll
        for (int j = 0; j < 16; ++j) {
            const float aj = __shfl_sync(0xffffffffu, e[j & 3], gbase + (j >> 2));
            const float2 vf = __half22float2(vh[j]);
            o2.x = fmaf(aj, vf.x, o2.x);
            o2.y = fmaf(aj, vf.y, o2.y);
        }
        *(float2*)&g_o[n * 64 + 2 * l] = o2;
    }
}

// ============================================================================
// Kernel 3: out = g_o @ Wo + bo. PERSISTENT + pipelined, same structure.
// Per i-step: 1 LDS.128 + 4 LDS.64 + 8 FFMA2.
// ============================================================================
__global__ void __launch_bounds__(256) out_proj_kernel(
    const float* __restrict__ Wo,
    const float* __restrict__ bo,
    float* __restrict__ out)
{
    __shared__ __align__(16) float wo_s[4096];
    __shared__ __align__(16) ull   fdup[64][64];

    const int tid = threadIdx.x;
    for (int i = tid; i < 4096; i += 256) wo_s[i] = Wo[i];

    const int c4 = tid & 15;
    const int pr = tid >> 4;

    const float2 b0 = *(const float2*)&bo[4 * c4];
    const float2 b1 = *(const float2*)&bo[4 * c4 + 2];
    const ull bias0 = packxy(b0.x, b0.y);
    const ull bias1 = packxy(b1.x, b1.y);

    float4 buf[4];
    int t = blockIdx.x;
    if (t < NTILES) load_tile(g_o, t * 64, buf);

    for (; t < NTILES; t += gridDim.x) {
        const int base = t * 64;
        store_tile_dup(fdup, buf);
        __syncthreads();

        const int tn = t + gridDim.x;
        if (tn < NTILES) load_tile(g_o, tn * 64, buf);

        ull acc[4][2];
        #pragma unroll
        for (int pp = 0; pp < 4; ++pp) { acc[pp][0] = bias0; acc[pp][1] = bias1; }

        #pragma unroll
        for (int i = 0; i < 64; ++i) {
            const ulonglong2 w01 = *(const ulonglong2*)&wo_s[i * 64 + 4 * c4];
            #pragma unroll
            for (int pp = 0; pp < 4; ++pp) {
                const ull f = fdup[pr + 16 * pp][i];
                acc[pp][0] = fma2(f, w01.x, acc[pp][0]);
                acc[pp][1] = fma2(f, w01.y, acc[pp][1]);
            }
        }

        #pragma unroll
        for (int pp = 0; pp < 4; ++pp) {
            const int n = base + pr + 16 * pp;
            if (n < NPTS) {
                *(ull*)&out[n * 64 + 4 * c4]     = acc[pp][0];
                *(ull*)&out[n * 64 + 4 * c4 + 2] = acc[pp][1];
            }
        }
        __syncthreads();
    }
}

// ============================================================================
extern "C" void kernel_launch(void* const* d_in, const int* in_sizes, int n_in,
                              void* d_out, int out_size) {
    const float* feats = (const float*)d_in[0];
    const int*   knn   = (const int*)  d_in[1];
    const float* Wq    = (const float*)d_in[2];
    const float* Wk    = (const float*)d_in[3];
    const float* Wv    = (const float*)d_in[4];
    const float* Wo    = (const float*)d_in[5];
    const float* bo    = (const float*)d_in[6];
    float* out = (float*)d_out;

    proj_qkv_kernel<<<296, 256>>>(feats, Wq, Wk, Wv);   // 2 blocks/SM, persistent
    attn_kernel<<<592, 256>>>(knn);                      // persistent grid-stride
    out_proj_kernel<<<592, 256>>>(Wo, bo, out);          // 4 blocks/SM, persistent
}

// round 11
// speedup vs baseline: 1.0571x; 1.0571x over previous
#include <cuda_runtime.h>
#include <cuda_fp16.h>
#include <cstdint>

#define NPTS 100000
#define NTILES 1563            // ceil(100000/64)
typedef unsigned long long ull;

// Scratch (device globals). q fp32; k,v fp16 interleaved: row = [k(64) | v(64)].
__device__ float  g_q[NPTS * 64];
__device__ __half g_kv[NPTS * 128];

// ---- packed f32x2 helpers ----
__device__ __forceinline__ ull pack2(float x) {
    ull r;
    asm("mov.b64 %0, {%1, %1};" : "=l"(r) : "r"(__float_as_uint(x)));
    return r;
}
__device__ __forceinline__ ull packxy(float x, float y) {
    ull r;
    asm("mov.b64 %0, {%1, %2};" : "=l"(r) : "f"(x), "f"(y));
    return r;
}
__device__ __forceinline__ float2 unpack2(ull a) {
    float2 f;
    asm("mov.b64 {%0, %1}, %2;" : "=f"(f.x), "=f"(f.y) : "l"(a));
    return f;
}
__device__ __forceinline__ ull fma2(ull a, ull b, ull c) {
    ull d;
    asm("fma.rn.f32x2 %0, %1, %2, %3;" : "=l"(d) : "l"(a), "l"(b), "l"(c));
    return d;
}

// load one 64-point tile into 4 float4 regs per thread (coalesced LDG.128)
__device__ __forceinline__ void load_tile(const float* __restrict__ src,
                                          int base, float4* buf) {
    #pragma unroll
    for (int k2 = 0; k2 < 4; ++k2) {
        const int fi = (threadIdx.x + k2 * 256) * 4;   // float index in tile
        const int n = base + (fi >> 6);
        buf[k2] = (n < NPTS) ? *(const float4*)&src[(size_t)base * 64 + fi]
                             : make_float4(0.f, 0.f, 0.f, 0.f);
    }
}

// store the 4 float4 regs into fdup as duplicated {f,f} pairs (STS.128 x2 each)
__device__ __forceinline__ void store_tile_dup(ull (*fdup)[64], const float4* buf) {
    #pragma unroll
    for (int k2 = 0; k2 < 4; ++k2) {
        const int fi = (threadIdx.x + k2 * 256) * 4;
        const int p = fi >> 6, c = fi & 63;
        ulonglong2 a, b;
        a.x = pack2(buf[k2].x); a.y = pack2(buf[k2].y);
        b.x = pack2(buf[k2].z); b.y = pack2(buf[k2].w);
        *(ulonglong2*)&fdup[p][c]     = a;
        *(ulonglong2*)&fdup[p][c + 2] = b;
    }
}

// ============================================================================
// Kernel 1: q,k,v = feats @ {Wq,Wk,Wv}. PERSISTENT: weights loaded once per
// block; loop over tiles with register-prefetched feats (LDG hidden by FFMA2).
// Thread = (4 channels, 4 points). Per i-step: 3 LDS.128 + 4 LDS.64 + 24 FFMA2.
// ============================================================================
__global__ void __launch_bounds__(256) proj_qkv_kernel(
    const float* __restrict__ feats,
    const float* __restrict__ Wq,
    const float* __restrict__ Wk,
    const float* __restrict__ Wv)
{
    __shared__ __align__(16) float wq_s[4096];
    __shared__ __align__(16) float wk_s[4096];
    __shared__ __align__(16) float wv_s[4096];
    __shared__ __align__(16) ull   fdup[64][64];   // 32 KB

    const int tid = threadIdx.x;
    for (int i = tid; i < 4096; i += 256) {
        wq_s[i] = Wq[i]; wk_s[i] = Wk[i]; wv_s[i] = Wv[i];
    }

    const int c4 = tid & 15;    // channels 4*c4 .. 4*c4+3
    const int pr = tid >> 4;    // points pr, pr+16, pr+32, pr+48

    float4 buf[4];
    int t = blockIdx.x;
    if (t < NTILES) load_tile(feats, t * 64, buf);

    for (; t < NTILES; t += gridDim.x) {
        const int base = t * 64;
        store_tile_dup(fdup, buf);
        __syncthreads();                       // fdup (and, first iter, weights) ready

        const int tn = t + gridDim.x;
        if (tn < NTILES) load_tile(feats, tn * 64, buf);   // prefetch next tile

        ull aq[4][2], ak[4][2], av[4][2];
        #pragma unroll
        for (int pp = 0; pp < 4; ++pp)
            #pragma unroll
            for (int h = 0; h < 2; ++h) { aq[pp][h] = 0; ak[pp][h] = 0; av[pp][h] = 0; }

        #pragma unroll
        for (int i = 0; i < 64; ++i) {
            const ulonglong2 wq01 = *(const ulonglong2*)&wq_s[i * 64 + 4 * c4];
            const ulonglong2 wk01 = *(const ulonglong2*)&wk_s[i * 64 + 4 * c4];
            const ulonglong2 wv01 = *(const ulonglong2*)&wv_s[i * 64 + 4 * c4];
            #pragma unroll
            for (int pp = 0; pp < 4; ++pp) {
                const ull f = fdup[pr + 16 * pp][i];    // broadcast LDS.64
                aq[pp][0] = fma2(f, wq01.x, aq[pp][0]);
                aq[pp][1] = fma2(f, wq01.y, aq[pp][1]);
                ak[pp][0] = fma2(f, wk01.x, ak[pp][0]);
                ak[pp][1] = fma2(f, wk01.y, ak[pp][1]);
                av[pp][0] = fma2(f, wv01.x, av[pp][0]);
                av[pp][1] = fma2(f, wv01.y, av[pp][1]);
            }
        }

        #pragma unroll
        for (int pp = 0; pp < 4; ++pp) {
            const int n = base + pr + 16 * pp;
            if (n < NPTS) {
                *(ull*)&g_q[n * 64 + 4 * c4]     = aq[pp][0];
                *(ull*)&g_q[n * 64 + 4 * c4 + 2] = aq[pp][1];
                const float2 k0 = unpack2(ak[pp][0]), k1 = unpack2(ak[pp][1]);
                const float2 v0 = unpack2(av[pp][0]), v1 = unpack2(av[pp][1]);
                *(__half2*)&g_kv[n * 128 + 4 * c4]          = __floats2half2_rn(k0.x, k0.y);
                *(__half2*)&g_kv[n * 128 + 4 * c4 + 2]      = __floats2half2_rn(k1.x, k1.y);
                *(__half2*)&g_kv[n * 128 + 64 + 4 * c4]     = __floats2half2_rn(v0.x, v0.y);
                *(__half2*)&g_kv[n * 128 + 64 + 4 * c4 + 2] = __floats2half2_rn(v1.x, v1.y);
            }
        }
        __syncthreads();                       // all reads of fdup done
    }
}

// ============================================================================
// Kernel 2 (FUSED): attention + output projection, persistent over 64-pt tiles.
// Phase 1: warp w computes attention for points base+8w .. base+8w+7 and
//          writes o straight into the duplicated-SMEM GEMM operand (STS.128).
// Phase 2: block runs the register-tiled  out = o @ Wo + bo  GEMM.
// g_o round trip (51 MB) and the out_proj kernel are eliminated.
// ============================================================================
__global__ void __launch_bounds__(256) attn_out_kernel(
    const int*   __restrict__ knn,
    const float* __restrict__ Wo,
    const float* __restrict__ bo,
    float*       __restrict__ out)
{
    __shared__ __align__(16) float wo_s[4096];   // 16 KB
    __shared__ __align__(16) ull   fdup[64][64]; // 32 KB (duplicated o)

    const int tid = threadIdx.x;
    const int w = tid >> 5;
    const int l = tid & 31;

    for (int i = tid; i < 4096; i += 256) wo_s[i] = Wo[i];

    const int c4 = tid & 15;
    const int pr = tid >> 4;
    const float2 b0 = *(const float2*)&bo[4 * c4];
    const float2 b1 = *(const float2*)&bo[4 * c4 + 2];
    const ull bias0 = packxy(b0.x, b0.y);
    const ull bias1 = packxy(b1.x, b1.y);

    for (int t = blockIdx.x; t < NTILES; t += gridDim.x) {
        const int base = t * 64;

        // ---- phase 1: attention for this warp's 8 points ----
        #pragma unroll 1
        for (int s = 0; s < 8; ++s) {
            const int p = w * 8 + s;
            const int n = base + p;
            if (n < NPTS) {
                int idxv = 0;
                if (l < 16) idxv = knn[n * 16 + l];
                int idxs[16];
                #pragma unroll
                for (int j = 0; j < 16; ++j)
                    idxs[j] = __shfl_sync(0xffffffffu, idxv, j);

                const float2 q2 = *(const float2*)&g_q[n * 64 + 2 * l];

                __half2 kh[16], vh[16];
                #pragma unroll
                for (int j = 0; j < 16; ++j) {
                    kh[j] = *(const __half2*)&g_kv[idxs[j] * 128 + 2 * l];
                    vh[j] = *(const __half2*)&g_kv[idxs[j] * 128 + 64 + 2 * l];
                }

                float a[16];
                #pragma unroll
                for (int j = 0; j < 16; ++j) {
                    const float2 kf = __half22float2(kh[j]);
                    float pscore = q2.x * kf.x + q2.y * kf.y;
                    pscore += __shfl_xor_sync(0xffffffffu, pscore, 1);
                    pscore += __shfl_xor_sync(0xffffffffu, pscore, 2);
                    a[j] = pscore * 0.3535533905932738f;   // * 1/sqrt(8)
                }

                float m = a[0];
                #pragma unroll
                for (int j = 1; j < 16; ++j) m = fmaxf(m, a[j]);
                float ssum = 0.f;
                #pragma unroll
                for (int j = 0; j < 16; ++j) {
                    a[j] = exp2f((a[j] - m) * 1.4426950408889634f);
                    ssum += a[j];
                }
                const float inv = __fdividef(1.f, ssum);

                float2 o2 = make_float2(0.f, 0.f);
                #pragma unroll
                for (int j = 0; j < 16; ++j) {
                    const float2 vf = __half22float2(vh[j]);
                    const float aj = a[j] * inv;
                    o2.x = fmaf(aj, vf.x, o2.x);
                    o2.y = fmaf(aj, vf.y, o2.y);
                }
                ulonglong2 od;
                od.x = pack2(o2.x); od.y = pack2(o2.y);
                *(ulonglong2*)&fdup[p][2 * l] = od;       // STS.128, conflict-free
            }
        }
        __syncthreads();

        // ---- phase 2: out = o @ Wo + bo (register-tiled, 4ch x 4pt) ----
        ull acc[4][2];
        #pragma unroll
        for (int pp = 0; pp < 4; ++pp) { acc[pp][0] = bias0; acc[pp][1] = bias1; }

        #pragma unroll
        for (int i = 0; i < 64; ++i) {
            const ulonglong2 w01 = *(const ulonglong2*)&wo_s[i * 64 + 4 * c4];
            #pragma unroll
            for (int pp = 0; pp < 4; ++pp) {
                const ull f = fdup[pr + 16 * pp][i];
                acc[pp][0] = fma2(f, w01.x, acc[pp][0]);
                acc[pp][1] = fma2(f, w01.y, acc[pp][1]);
            }
        }

        #pragma unroll
        for (int pp = 0; pp < 4; ++pp) {
            const int n = base + pr + 16 * pp;
            if (n < NPTS) {
                *(ull*)&out[n * 64 + 4 * c4]     = acc[pp][0];
                *(ull*)&out[n * 64 + 4 * c4 + 2] = acc[pp][1];
            }
        }
        __syncthreads();
    }
}

// ============================================================================
extern "C" void kernel_launch(void* const* d_in, const int* in_sizes, int n_in,
                              void* d_out, int out_size) {
    const float* feats = (const float*)d_in[0];
    const int*   knn   = (const int*)  d_in[1];
    const float* Wq    = (const float*)d_in[2];
    const float* Wk    = (const float*)d_in[3];
    const float* Wv    = (const float*)d_in[4];
    const float* Wo    = (const float*)d_in[5];
    const float* bo    = (const float*)d_in[6];
    float* out = (float*)d_out;

    proj_qkv_kernel<<<296, 256>>>(feats, Wq, Wk, Wv);   // 2 blocks/SM, persistent
    attn_out_kernel<<<592, 256>>>(knn, Wo, bo, out);    // fused attn + out-proj
}